// round 2
// baseline (speedup 1.0000x reference)
#include <cuda_runtime.h>
#include <cstddef>

// Problem constants (match reference)
#define BB 4
#define CC 256
#define HH 512
#define WW 512
#define NROIS 32
#define OUT 7

// One CTA per (roi, b, c). Stage ROI region into smem coalesced, then
// 49 threads each reduce one adaptive-pool bin.
__global__ __launch_bounds__(128, 8)
void roi_adaptive_pool_kernel(const float* __restrict__ x,
                              const void* __restrict__ rois_raw,
                              float* __restrict__ out)
{
    // bid = roi * (BB*CC) + b*CC + c
    int bid = blockIdx.x;
    int c   = bid % CC;
    int t   = bid / CC;
    int b   = t % BB;
    int roi = t / BB;

    // ---- dtype probe: rois may be int64 (reference) or int32 (harness) ----
    // Reading the first 32 bytes as int64 is safe in both layouts
    // (int32 buffer is 128*4 = 512 bytes).
    const long long* r64 = (const long long*)rois_raw;
    const int*       r32 = (const int*)rois_raw;

    long long p0 = r64[0], p1 = r64[1], p2 = r64[2], p3 = r64[3];
    bool is64 = (p0 >= 0 && p0 <= WW) && (p1 >= 0 && p1 <= HH) &&
                (p2 > p0 && p2 <= WW) && (p3 > p1 && p3 <= HH);
    // If data is int32, word1 = x2 + (y2<<32) with y2>=16 -> fails checks.

    int x1, y1, x2, y2;
    if (is64) {
        const long long* r = r64 + (size_t)roi * 4;
        x1 = (int)r[0]; y1 = (int)r[1]; x2 = (int)r[2]; y2 = (int)r[3];
    } else {
        const int* r = r32 + (size_t)roi * 4;
        x1 = r[0]; y1 = r[1]; x2 = r[2]; y2 = r[3];
    }

    int w = x2 - x1;          // 16..63
    int h = y2 - y1;          // 16..63

    __shared__ float tile[64 * 64];   // 16 KB, fits max ROI

    const float* src = x + (((size_t)(b * CC + c)) * HH + (size_t)y1) * WW + x1;

    int n = h * w;
    for (int idx = threadIdx.x; idx < n; idx += blockDim.x) {
        int rr  = idx / w;
        int col = idx - rr * w;
        tile[idx] = __ldg(src + (size_t)rr * WW + col);
    }
    __syncthreads();

    int tb = threadIdx.x;
    if (tb < OUT * OUT) {
        int i = tb / OUT;
        int j = tb - i * OUT;
        int hs = (i * h) / OUT;
        int he = ((i + 1) * h + OUT - 1) / OUT;
        int ws = (j * w) / OUT;
        int we = ((j + 1) * w + OUT - 1) / OUT;

        float s = 0.0f;
        for (int rr = hs; rr < he; ++rr) {
            const float* row = tile + rr * w;
            #pragma unroll 4
            for (int cc = ws; cc < we; ++cc)
                s += row[cc];
        }
        float area = (float)((he - hs) * (we - ws));

        // out[b][roi*CC + c][i][j]
        size_t oidx = ((((size_t)b * (NROIS * CC)) + (size_t)roi * CC + c) * OUT + i) * OUT + j;
        out[oidx] = s / area;
    }
}

extern "C" void kernel_launch(void* const* d_in, const int* in_sizes, int n_in,
                              void* d_out, int out_size)
{
    const float* x    = (const float*)d_in[0];
    const void*  rois = d_in[1];
    float*       out  = (float*)d_out;

    dim3 grid(NROIS * BB * CC);   // 32768 CTAs
    dim3 block(128);
    roi_adaptive_pool_kernel<<<grid, block>>>(x, rois, out);
}

// round 3
// speedup vs baseline: 1.1324x; 1.1324x over previous
#include <cuda_runtime.h>
#include <cstddef>

// Problem constants (match reference)
#define BB 4
#define CC 256
#define HH 512
#define WW 512
#define NROIS 32
#define OUT 7

// One CTA per (roi, b, c).
// Phase 1: warp-per-row coalesced staging of the ROI region into smem
//          (no integer division anywhere in the hot loop).
// Phase 2: threads 0..48 each reduce one adaptive-pool bin.
__global__ __launch_bounds__(128)
void roi_adaptive_pool_kernel(const float* __restrict__ x,
                              const void* __restrict__ rois_raw,
                              float* __restrict__ out)
{
    // bid = roi * (BB*CC) + b*CC + c
    int bid = blockIdx.x;
    int c   = bid & (CC - 1);
    int t   = bid >> 8;           // / CC
    int b   = t & (BB - 1);
    int roi = t >> 2;             // / BB

    // ---- dtype probe: rois may be int64 (reference) or int32 (harness) ----
    const long long* r64 = (const long long*)rois_raw;
    const int*       r32 = (const int*)rois_raw;

    long long p0 = r64[0], p1 = r64[1], p2 = r64[2], p3 = r64[3];
    bool is64 = (p0 >= 0 && p0 <= WW) && (p1 >= 0 && p1 <= HH) &&
                (p2 > p0 && p2 <= WW) && (p3 > p1 && p3 <= HH);

    int x1, y1, x2, y2;
    if (is64) {
        const long long* r = r64 + (size_t)roi * 4;
        x1 = (int)r[0]; y1 = (int)r[1]; x2 = (int)r[2]; y2 = (int)r[3];
    } else {
        const int* r = r32 + (size_t)roi * 4;
        x1 = r[0]; y1 = r[1]; x2 = r[2]; y2 = r[3];
    }

    int w = x2 - x1;          // 16..63
    int h = y2 - y1;          // 16..63

    __shared__ float tile[64 * 64];   // 16 KB, fits max ROI (compact row stride w)

    const float* src = x + (((size_t)(b * CC + c)) * HH + (size_t)y1) * WW + x1;

    // Phase 1: warp per row, lanes stride columns. No division.
    int lane = threadIdx.x & 31;
    int warp = threadIdx.x >> 5;
    {
        const float* srow = src + (size_t)warp * WW;
        float*       drow = tile + warp * w;
        for (int rr = warp; rr < h; rr += 4) {
            for (int col = lane; col < w; col += 32)
                drow[col] = __ldg(srow + col);
            srow += 4 * (size_t)WW;
            drow += 4 * w;
        }
    }
    __syncthreads();

    // Phase 2: one thread per output bin.
    int tb = threadIdx.x;
    if (tb < OUT * OUT) {
        int i = tb / OUT;             // compile-time-constant divisor -> cheap
        int j = tb - i * OUT;
        int hs = (i * h) / OUT;
        int he = ((i + 1) * h + OUT - 1) / OUT;
        int ws = (j * w) / OUT;
        int we = ((j + 1) * w + OUT - 1) / OUT;

        float s = 0.0f;
        const float* row = tile + hs * w;
        for (int rr = hs; rr < he; ++rr, row += w) {
            #pragma unroll 3
            for (int cc = ws; cc < we; ++cc)
                s += row[cc];
        }
        float area = (float)((he - hs) * (we - ws));

        // out[b][roi*CC + c][i][j]
        size_t oidx = ((((size_t)b * (NROIS * CC)) + (size_t)roi * CC + c) * (OUT * OUT)) + tb;
        out[oidx] = s / area;
    }
}

extern "C" void kernel_launch(void* const* d_in, const int* in_sizes, int n_in,
                              void* d_out, int out_size)
{
    const float* x    = (const float*)d_in[0];
    const void*  rois = d_in[1];
    float*       out  = (float*)d_out;

    dim3 grid(NROIS * BB * CC);   // 32768 CTAs
    dim3 block(128);
    roi_adaptive_pool_kernel<<<grid, block>>>(x, rois, out);
}

// round 4
// speedup vs baseline: 1.8230x; 1.6098x over previous
#include <cuda_runtime.h>
#include <cstddef>
#include <cstdint>

// Problem constants (match reference)
#define BB 4
#define CC 256
#define HH 512
#define WW 512
#define NROIS 32
#define OUT 7

__device__ __forceinline__ void cp_async4(uint32_t smem_dst, const void* gmem_src) {
    asm volatile("cp.async.ca.shared.global [%0], [%1], 4;\n"
                 :: "r"(smem_dst), "l"(gmem_src));
}
__device__ __forceinline__ void cp_async_commit_wait() {
    asm volatile("cp.async.commit_group;\n"
                 "cp.async.wait_group 0;\n" ::: "memory");
}

// One CTA per (roi, b, c).
// Phase 1: warp-per-row staging via cp.async (no LDG->STS register dependency,
//          deep MLP, fire-and-forget).
// Phase 2: threads 0..48 each reduce one adaptive-pool bin (2-way row ILP).
__global__ __launch_bounds__(128)
void roi_adaptive_pool_kernel(const float* __restrict__ x,
                              const void* __restrict__ rois_raw,
                              float* __restrict__ out)
{
    int bid = blockIdx.x;
    int c   = bid & (CC - 1);
    int t   = bid >> 8;           // / CC
    int b   = t & (BB - 1);
    int roi = t >> 2;             // / BB

    // ---- dtype probe: rois may be int64 (reference) or int32 (harness) ----
    const long long* r64 = (const long long*)rois_raw;
    const int*       r32 = (const int*)rois_raw;

    long long p0 = r64[0], p1 = r64[1], p2 = r64[2], p3 = r64[3];
    bool is64 = (p0 >= 0 && p0 <= WW) && (p1 >= 0 && p1 <= HH) &&
                (p2 > p0 && p2 <= WW) && (p3 > p1 && p3 <= HH);

    int x1, y1, x2, y2;
    if (is64) {
        const long long* r = r64 + (size_t)roi * 4;
        x1 = (int)r[0]; y1 = (int)r[1]; x2 = (int)r[2]; y2 = (int)r[3];
    } else {
        const int* r = r32 + (size_t)roi * 4;
        x1 = r[0]; y1 = r[1]; x2 = r[2]; y2 = r[3];
    }

    int w = x2 - x1;          // 16..63
    int h = y2 - y1;          // 16..63

    __shared__ float tile[64 * 64];   // 16 KB, compact row stride w

    const float* src = x + (((size_t)(b * CC + c)) * HH + (size_t)y1) * WW + x1;

    // Phase 1: warp per row (stride 4 rows), lanes cover columns.
    // w <= 63 -> at most two column positions per lane (lane, lane+32).
    int lane = threadIdx.x & 31;
    int warp = threadIdx.x >> 5;
    {
        uint32_t smem_base = (uint32_t)__cvta_generic_to_shared(tile);
        const float* srow = src + (size_t)warp * WW + lane;
        uint32_t     drow = smem_base + (uint32_t)(warp * w + lane) * 4u;
        bool do0 = lane < w;
        bool do1 = lane + 32 < w;
        for (int rr = warp; rr < h; rr += 4) {
            if (do0) cp_async4(drow, srow);
            if (do1) cp_async4(drow + 128, srow + 32);
            srow += 4 * (size_t)WW;
            drow += 4u * (uint32_t)w * 4u;
        }
    }
    cp_async_commit_wait();
    __syncthreads();

    // Phase 2: one thread per output bin, two-row accumulator ILP.
    int tb = threadIdx.x;
    if (tb < OUT * OUT) {
        int i = tb / OUT;
        int j = tb - i * OUT;
        int hs = (i * h) / OUT;
        int he = ((i + 1) * h + OUT - 1) / OUT;
        int ws = (j * w) / OUT;
        int we = ((j + 1) * w + OUT - 1) / OUT;

        float s0 = 0.0f, s1 = 0.0f;
        const float* row = tile + hs * w + ws;
        int nc = we - ws;
        int rr = hs;
        for (; rr + 1 < he; rr += 2) {
            const float* rA = row;
            const float* rB = row + w;
            #pragma unroll 3
            for (int cc = 0; cc < nc; ++cc) {
                s0 += rA[cc];
                s1 += rB[cc];
            }
            row += 2 * w;
        }
        if (rr < he) {
            #pragma unroll 3
            for (int cc = 0; cc < nc; ++cc)
                s0 += row[cc];
        }
        float s = s0 + s1;
        float area = (float)((he - hs) * nc);

        size_t oidx = ((((size_t)b * (NROIS * CC)) + (size_t)roi * CC + c) * (OUT * OUT)) + tb;
        out[oidx] = s / area;
    }
}

extern "C" void kernel_launch(void* const* d_in, const int* in_sizes, int n_in,
                              void* d_out, int out_size)
{
    const float* x    = (const float*)d_in[0];
    const void*  rois = d_in[1];
    float*       out  = (float*)d_out;

    dim3 grid(NROIS * BB * CC);   // 32768 CTAs
    dim3 block(128);
    roi_adaptive_pool_kernel<<<grid, block>>>(x, rois, out);
}

// round 5
// speedup vs baseline: 2.2515x; 1.2351x over previous
#include <cuda_runtime.h>
#include <cstddef>
#include <cstdint>

// Problem constants (match reference)
#define BB 4
#define CC 256
#define HH 512
#define WW 512
#define NROIS 32
#define OUT 7
#define TS 68   // smem tile row stride in floats (16B-aligned, fits w<=63 + align slop)

__device__ __forceinline__ void cp_async16(uint32_t smem_dst, const void* gmem_src) {
    asm volatile("cp.async.cg.shared.global [%0], [%1], 16;\n"
                 :: "r"(smem_dst), "l"(gmem_src));
}
__device__ __forceinline__ void cp_async_commit_wait() {
    asm volatile("cp.async.commit_group;\n"
                 "cp.async.wait_group 0;\n" ::: "memory");
}

// One CTA per (roi, b, c).
// Phase 1: warp-per-row staging via 16B-aligned cp.async.cg chunks.
// Phase 2: threads 0..48 each reduce one adaptive-pool bin (2-way row ILP).
__global__ __launch_bounds__(128)
void roi_adaptive_pool_kernel(const float* __restrict__ x,
                              const void* __restrict__ rois_raw,
                              float* __restrict__ out)
{
    int bid = blockIdx.x;
    int c   = bid & (CC - 1);
    int t   = bid >> 8;           // / CC
    int b   = t & (BB - 1);
    int roi = t >> 2;             // / BB

    // ---- dtype probe: rois may be int64 (reference) or int32 (harness) ----
    const long long* r64 = (const long long*)rois_raw;
    const int*       r32 = (const int*)rois_raw;

    long long p0 = r64[0], p1 = r64[1], p2 = r64[2], p3 = r64[3];
    bool is64 = (p0 >= 0 && p0 <= WW) && (p1 >= 0 && p1 <= HH) &&
                (p2 > p0 && p2 <= WW) && (p3 > p1 && p3 <= HH);

    int x1, y1, x2, y2;
    if (is64) {
        const long long* r = r64 + (size_t)roi * 4;
        x1 = (int)r[0]; y1 = (int)r[1]; x2 = (int)r[2]; y2 = (int)r[3];
    } else {
        const int* r = r32 + (size_t)roi * 4;
        x1 = r[0]; y1 = r[1]; x2 = r[2]; y2 = r[3];
    }

    int w = x2 - x1;          // 16..63
    int h = y2 - y1;          // 16..63

    int xa = x1 & ~3;                  // 16B-aligned row start
    int ox = x1 - xa;                  // 0..3 intra-chunk offset
    int nc = (x2 - xa + 3) >> 2;       // float4 chunks per row (<=17)

    __shared__ float tile[64 * TS];    // 17408 B

    const float* plane = x + ((size_t)(b * CC + c)) * (HH * WW);

    // Phase 1: warp per row (stride 4 rows), lane = chunk index.
    int lane = threadIdx.x & 31;
    int warp = threadIdx.x >> 5;
    if (lane < nc) {
        uint32_t sbase = (uint32_t)__cvta_generic_to_shared(tile);
        const float4* sp = (const float4*)(plane + ((size_t)(y1 + warp)) * WW + xa) + lane;
        uint32_t      dp = sbase + (uint32_t)(warp * TS + lane * 4) * 4u;
        for (int rr = warp; rr < h; rr += 4) {
            cp_async16(dp, sp);
            sp += 4 * (WW / 4);        // 4 rows, in float4 units
            dp += 4u * TS * 4u;
        }
    }
    cp_async_commit_wait();
    __syncthreads();

    // Phase 2: one thread per output bin, two-row accumulator ILP.
    int tb = threadIdx.x;
    if (tb < OUT * OUT) {
        int i = tb / OUT;
        int j = tb - i * OUT;
        int hs = (i * h) / OUT;
        int he = ((i + 1) * h + OUT - 1) / OUT;
        int ws = (j * w) / OUT;
        int we = ((j + 1) * w + OUT - 1) / OUT;

        float s0 = 0.0f, s1 = 0.0f;
        const float* row = tile + hs * TS + ox + ws;
        int ncol = we - ws;
        int rr = hs;
        for (; rr + 1 < he; rr += 2) {
            const float* rA = row;
            const float* rB = row + TS;
            #pragma unroll 3
            for (int cc = 0; cc < ncol; ++cc) {
                s0 += rA[cc];
                s1 += rB[cc];
            }
            row += 2 * TS;
        }
        if (rr < he) {
            #pragma unroll 3
            for (int cc = 0; cc < ncol; ++cc)
                s0 += row[cc];
        }
        float s = s0 + s1;
        float area = (float)((he - hs) * ncol);

        size_t oidx = ((((size_t)b * (NROIS * CC)) + (size_t)roi * CC + c) * (OUT * OUT)) + tb;
        out[oidx] = s / area;
    }
}

extern "C" void kernel_launch(void* const* d_in, const int* in_sizes, int n_in,
                              void* d_out, int out_size)
{
    const float* x    = (const float*)d_in[0];
    const void*  rois = d_in[1];
    float*       out  = (float*)d_out;

    dim3 grid(NROIS * BB * CC);   // 32768 CTAs
    dim3 block(128);
    roi_adaptive_pool_kernel<<<grid, block>>>(x, rois, out);
}